// round 15
// baseline (speedup 1.0000x reference)
#include <cuda_runtime.h>
#include <cuda_bf16.h>
#include <math.h>
#include <stdint.h>

// Problem constants
#define NROWS 8192
#define DIMS  256
#define NT    64                     // 8192 / 128 tiles per side
#define NPAIR (NT * (NT + 1) / 2)    // 2080 upper-triangular tiles
#define EPS_F 1e-8f

// Tiling: CTA 128x128, 8 warps (2x4), warp 64x32, BK=32, 3-stage pipeline
#define BM 128
#define BK 32
#define NCHUNK (DIMS / BK)           // 8
#define NSTAGE 3
#define STAGE_ELEMS (2 * BM * BK)    // A + B per stage (bf16 elems)
#define SMEM_BYTES (NSTAGE * STAGE_ELEMS * 2)   // 49152

// Scratch (static device globals: allocation-free)
__device__ __nv_bfloat16 g_z1nb[NROWS * DIMS];  // normalized z1, row-major bf16
__device__ float  g_sq[NROWS];                  // fp32 |row|^2 after normalize
__device__ float  g_spos[NROWS];                // per-row positive-pair score
__device__ double g_partial[NPAIR];             // per-tile weighted exp sums
__device__ int    g_count = 0;                  // completion counter (self-reset)

// ---------------------------------------------------------------------------
// SMEM tile layout: row-major 128 x 32 bf16 (64B rows), XOR swizzle on 16B
// atoms; conflict-free for ldmatrix 8-row phases and cp.async 16B stores.
__device__ __forceinline__ int swz(int r, int atom) {
    return r * 32 + ((atom ^ ((r >> 1) & 3)) << 3);
}

__device__ __forceinline__ float warp_sum(float v) {
    #pragma unroll
    for (int o = 16; o > 0; o >>= 1)
        v += __shfl_xor_sync(0xffffffffu, v, o);
    return v;
}

// ---------------------------------------------------------------------------
// prep: warp-per-row normalize (no block barriers). grid = 1024 x 256 thr.
// Each warp owns one row; each lane owns 8 consecutive floats.
// ---------------------------------------------------------------------------
__global__ void prep_kernel(const float* __restrict__ z1,
                            const float* __restrict__ z2) {
    int gw   = (blockIdx.x * blockDim.x + threadIdx.x) >> 5;  // row index
    int lane = threadIdx.x & 31;

    const float4* p1 = (const float4*)(z1 + (size_t)gw * DIMS) + lane * 2;
    const float4* p2 = (const float4*)(z2 + (size_t)gw * DIMS) + lane * 2;
    float4 a0 = p1[0], a1 = p1[1];
    float4 b0 = p2[0], b1 = p2[1];

    float s1 = a0.x*a0.x + a0.y*a0.y + a0.z*a0.z + a0.w*a0.w
             + a1.x*a1.x + a1.y*a1.y + a1.z*a1.z + a1.w*a1.w;
    float s2 = b0.x*b0.x + b0.y*b0.y + b0.z*b0.z + b0.w*b0.w
             + b1.x*b1.x + b1.y*b1.y + b1.z*b1.z + b1.w*b1.w;
    s1 = warp_sum(s1);
    s2 = warp_sum(s2);

    float m1 = fmaxf(sqrtf(s1), 1e-12f);
    float m2 = fmaxf(sqrtf(s2), 1e-12f);
    float r1 = 1.0f / m1;
    float r2 = 1.0f / m2;

    float an[8] = { a0.x*r1, a0.y*r1, a0.z*r1, a0.w*r1,
                    a1.x*r1, a1.y*r1, a1.z*r1, a1.w*r1 };
    float bn[8] = { b0.x*r2, b0.y*r2, b0.z*r2, b0.w*r2,
                    b1.x*r2, b1.y*r2, b1.z*r2, b1.w*r2 };

    // pack 8 bf16 = 16B, coalesced store
    __nv_bfloat162 h[4];
    #pragma unroll
    for (int k = 0; k < 4; ++k)
        h[k] = __floats2bfloat162_rn(an[2*k], an[2*k+1]);
    *(uint4*)(g_z1nb + (size_t)gw * DIMS + lane * 8) = *(uint4*)h;

    float dp = 0.f;
    #pragma unroll
    for (int k = 0; k < 8; ++k) {
        float d = an[k] - bn[k];
        dp += d * d;
    }
    dp = warp_sum(dp);

    if (lane == 0) {
        g_sq[gw] = s1 * (r1 * r1);
        g_spos[gw] = logf(__expf(-0.5f * dp) + EPS_F) + 1.0f;
    }
}

// ---------------------------------------------------------------------------
// pair kernel: bf16 mma.sync Gram + exp + reduce, linear triangular grid,
// 3-stage cp.async pipeline with ONE __syncthreads per k-chunk, fused
// last-CTA finalize. 256 threads = 8 warps (2x4), warp tile 64x32.
// ---------------------------------------------------------------------------
extern __shared__ __align__(16) __nv_bfloat16 smem_tiles[];

__global__ void __launch_bounds__(256, 2) pair_kernel(float* __restrict__ out) {
    __shared__ float s_sq[256];
    __shared__ float red[8];
    __shared__ int s_last;

    int tid = threadIdx.x;
    int lane = tid & 31;
    int wid = tid >> 5;
    int wm = wid >> 2;   // 0..1 -> m offset wm*64
    int wn = wid & 3;    // 0..3 -> n offset wn*32

    // linear index -> (ti, tj), tj >= ti  (row ti holds NT - ti tiles)
    int rem = blockIdx.x;
    int ti = 0;
    while (rem >= NT - ti) { rem -= NT - ti; ++ti; }
    int tj = ti + rem;

    const __nv_bfloat16* gA = g_z1nb + (size_t)ti * BM * DIMS;
    const __nv_bfloat16* gB = g_z1nb + (size_t)tj * BM * DIMS;

    // stage sq values for the epilogue
    if (tid < 128) s_sq[tid] = g_sq[ti * BM + tid];
    else           s_sq[tid] = g_sq[tj * BM + (tid - 128)];

    float acc[4][4][4];
    #pragma unroll
    for (int mt = 0; mt < 4; ++mt)
        #pragma unroll
        for (int nt = 0; nt < 4; ++nt)
            #pragma unroll
            for (int r = 0; r < 4; ++r)
                acc[mt][nt][r] = 0.f;

    auto issue = [&](int stage, int kt) {
        __nv_bfloat16* As = smem_tiles + stage * STAGE_ELEMS;
        __nv_bfloat16* Bs = As + BM * BK;
        #pragma unroll
        for (int s = 0; s < 2; ++s) {
            int idx  = tid + (s << 8);      // 0..511
            int r    = idx >> 2;            // 0..127
            int atom = idx & 3;             // 0..3
            int off  = swz(r, atom);
            unsigned da = (unsigned)__cvta_generic_to_shared(&As[off]);
            unsigned db = (unsigned)__cvta_generic_to_shared(&Bs[off]);
            const __nv_bfloat16* sa = gA + r * DIMS + kt * BK + (atom << 3);
            const __nv_bfloat16* sb = gB + r * DIMS + kt * BK + (atom << 3);
            asm volatile("cp.async.cg.shared.global [%0], [%1], 16;\n"
                         :: "r"(da), "l"(sa));
            asm volatile("cp.async.cg.shared.global [%0], [%1], 16;\n"
                         :: "r"(db), "l"(sb));
        }
        asm volatile("cp.async.commit_group;\n");
    };

    issue(0, 0);
    issue(1, 1);

    int sel = lane >> 3;   // ldmatrix quadrant
    int l7  = lane & 7;

    for (int c = 0; c < NCHUNK; ++c) {
        if (c == NCHUNK - 1) asm volatile("cp.async.wait_group 0;\n");
        else                 asm volatile("cp.async.wait_group 1;\n");
        __syncthreads();
        if (c + 2 < NCHUNK) issue((c + 2) % NSTAGE, c + 2);

        const __nv_bfloat16* As = smem_tiles + (c % NSTAGE) * STAGE_ELEMS;
        const __nv_bfloat16* Bs = As + BM * BK;

        #pragma unroll
        for (int kk = 0; kk < BK; kk += 16) {
            unsigned af[4][4];
            unsigned bf_[4][2];

            #pragma unroll
            for (int mt = 0; mt < 4; ++mt) {
                int row  = wm * 64 + mt * 16 + ((sel & 1) << 3) + l7;
                int atom = (kk >> 3) + (sel >> 1);
                unsigned ad = (unsigned)__cvta_generic_to_shared(
                    &As[swz(row, atom)]);
                asm volatile(
                    "ldmatrix.sync.aligned.m8n8.x4.shared.b16 "
                    "{%0,%1,%2,%3}, [%4];\n"
                    : "=r"(af[mt][0]), "=r"(af[mt][1]),
                      "=r"(af[mt][2]), "=r"(af[mt][3])
                    : "r"(ad));
            }
            #pragma unroll
            for (int np = 0; np < 2; ++np) {
                int row  = wn * 32 + np * 16 + ((sel >> 1) << 3) + l7;
                int atom = (kk >> 3) + (sel & 1);
                unsigned bd = (unsigned)__cvta_generic_to_shared(
                    &Bs[swz(row, atom)]);
                asm volatile(
                    "ldmatrix.sync.aligned.m8n8.x4.shared.b16 "
                    "{%0,%1,%2,%3}, [%4];\n"
                    : "=r"(bf_[2 * np][0]), "=r"(bf_[2 * np][1]),
                      "=r"(bf_[2 * np + 1][0]), "=r"(bf_[2 * np + 1][1])
                    : "r"(bd));
            }

            #pragma unroll
            for (int mt = 0; mt < 4; ++mt)
                #pragma unroll
                for (int nt = 0; nt < 4; ++nt)
                    asm volatile(
                        "mma.sync.aligned.m16n8k16.row.col.f32.bf16.bf16.f32 "
                        "{%0,%1,%2,%3}, {%4,%5,%6,%7}, {%8,%9}, {%0,%1,%2,%3};\n"
                        : "+f"(acc[mt][nt][0]), "+f"(acc[mt][nt][1]),
                          "+f"(acc[mt][nt][2]), "+f"(acc[mt][nt][3])
                        : "r"(af[mt][0]), "r"(af[mt][1]),
                          "r"(af[mt][2]), "r"(af[mt][3]),
                          "r"(bf_[nt][0]), "r"(bf_[nt][1]));
        }
    }

    // epilogue: d2 = max(sq_i + sq_j - 2*dot, 0); e = exp(-0.5*d2); mask diag
    int grow  = lane >> 2;
    int gcol2 = (lane & 3) << 1;
    float sum = 0.f;
    #pragma unroll
    for (int mt = 0; mt < 4; ++mt) {
        #pragma unroll
        for (int nt = 0; nt < 4; ++nt) {
            #pragma unroll
            for (int r = 0; r < 4; ++r) {
                int li = wm * 64 + mt * 16 + grow + ((r & 2) ? 8 : 0);
                int lj = wn * 32 + nt * 8 + gcol2 + (r & 1);
                float d2 = fmaxf(s_sq[li] + s_sq[128 + lj]
                                 - 2.0f * acc[mt][nt][r], 0.0f);
                float e = __expf(-0.5f * d2);
                if (ti == tj && li == lj) e = 0.f;   // diagonal mask
                sum += e;
            }
        }
    }

    // block reduce -> one partial store per CTA (x2 weight off-diagonal)
    sum = warp_sum(sum);
    if (lane == 0) red[wid] = sum;
    __syncthreads();

    if (tid == 0) {
        float s = 0.f;
        #pragma unroll
        for (int w = 0; w < 8; ++w) s += red[w];
        double contrib = (double)s;
        if (ti != tj) contrib *= 2.0;
        g_partial[blockIdx.x] = contrib;
        __threadfence();
        int t = atomicAdd(&g_count, 1);
        s_last = (t == NPAIR - 1);
    }
    __syncthreads();

    // last CTA: fused finalize
    if (s_last) {
        __threadfence();
        if (tid == 0) g_count = 0;   // reset for next graph replay

        double dneg = 0.0;
        for (int i = tid; i < NPAIR; i += 256) dneg += g_partial[i];
        #pragma unroll
        for (int o = 16; o > 0; o >>= 1)
            dneg += __shfl_xor_sync(0xffffffffu, dneg, o);
        __shared__ double dred[8];
        if (lane == 0) dred[wid] = dneg;

        float ps = 0.f;
        for (int i = tid; i < NROWS; i += 256) ps += g_spos[i];
        ps = warp_sum(ps);
        __shared__ float fred[8];
        if (lane == 0) fred[wid] = ps;
        __syncthreads();

        if (tid == 0) {
            double neg = 0.0;
            float pos = 0.f;
            #pragma unroll
            for (int w = 0; w < 8; ++w) { neg += dred[w]; pos += fred[w]; }
            double n = (double)NROWS;
            double mean_star = neg / (n * (n - 1.0)) + 1e-8;
            out[0] = (float)(-((double)pos / n) + 1.5 * mean_star);
        }
    }
}

// ---------------------------------------------------------------------------
extern "C" void kernel_launch(void* const* d_in, const int* in_sizes, int n_in,
                              void* d_out, int out_size) {
    const float* z1 = (const float*)d_in[0];
    const float* z2 = (const float*)d_in[1];
    float* out = (float*)d_out;

    cudaFuncSetAttribute(pair_kernel,
                         cudaFuncAttributeMaxDynamicSharedMemorySize,
                         SMEM_BYTES);

    prep_kernel<<<NROWS / 8, 256>>>(z1, z2);
    pair_kernel<<<NPAIR, 256, SMEM_BYTES>>>(out);
}

// round 17
// speedup vs baseline: 1.0865x; 1.0865x over previous
#include <cuda_runtime.h>
#include <cuda_bf16.h>
#include <math.h>
#include <stdint.h>

// Problem constants
#define NROWS 8192
#define DIMS  256
#define NT    64                     // 8192 / 128 tiles per side
#define NPAIR (NT * (NT + 1) / 2)    // 2080 upper-triangular tiles
#define EPS_F 1e-8f
#define QSCALE 16.0f                 // row pre-scale into e4m3 range
#define DOT_SCL (1.0f / (QSCALE * QSCALE))

// Tiling (R3-validated structure): CTA 128x128, 8 warps (2x4), warp 64x32.
// BK = 64 fp8 elements = 64-byte smem rows (4 x 16B atoms), double-buffered.
#define BM 128
#define BK 64
#define NCHUNK (DIMS / BK)           // 4

// Scratch (static device globals: allocation-free)
__device__ uint8_t g_z1f8[NROWS * DIMS];   // 16*normalized z1, e4m3, row-major
__device__ float   g_sq[NROWS];            // fp32 |row|^2 after normalize
__device__ float   g_spos[NROWS];          // per-row positive-pair score
__device__ double  g_partial[NPAIR];       // per-tile weighted exp sums
__device__ int     g_count = 0;            // completion counter (self-reset)

// ---------------------------------------------------------------------------
// helpers
// ---------------------------------------------------------------------------
__device__ __forceinline__ float warp_sum(float v) {
    #pragma unroll
    for (int o = 16; o > 0; o >>= 1)
        v += __shfl_xor_sync(0xffffffffu, v, o);
    return v;
}

// pack two floats -> e4m3x2 (lo = first arg)
__device__ __forceinline__ uint16_t f2e4m3x2(float lo, float hi) {
    uint16_t r;
    asm("cvt.rn.satfinite.e4m3x2.f32 %0, %1, %2;" : "=h"(r) : "f"(hi), "f"(lo));
    return r;
}

// SMEM tile layout: row-major 128 x 64 BYTES, XOR swizzle on 16B atoms
// (same pattern as validated bf16 kernel: atom ^ ((r>>1)&3)); conflict-free
// for ldmatrix 8-row phases and cp.async 16B stores. Returns BYTE offset.
__device__ __forceinline__ int swz(int r, int atom) {
    return r * 64 + ((atom ^ ((r >> 1) & 3)) << 4);
}

// ---------------------------------------------------------------------------
// prep: warp-per-row normalize; emit e4m3 16*z1n, sq, s_pos (plain stores)
// grid = NROWS/8 blocks x 256 threads; each warp owns one row.
// ---------------------------------------------------------------------------
__global__ void prep_kernel(const float* __restrict__ z1,
                            const float* __restrict__ z2) {
    int gw   = (blockIdx.x * blockDim.x + threadIdx.x) >> 5;  // row index
    int lane = threadIdx.x & 31;

    const float4* p1 = (const float4*)(z1 + (size_t)gw * DIMS) + lane * 2;
    const float4* p2 = (const float4*)(z2 + (size_t)gw * DIMS) + lane * 2;
    float4 a0 = p1[0], a1 = p1[1];
    float4 b0 = p2[0], b1 = p2[1];

    float s1 = a0.x*a0.x + a0.y*a0.y + a0.z*a0.z + a0.w*a0.w
             + a1.x*a1.x + a1.y*a1.y + a1.z*a1.z + a1.w*a1.w;
    float s2 = b0.x*b0.x + b0.y*b0.y + b0.z*b0.z + b0.w*b0.w
             + b1.x*b1.x + b1.y*b1.y + b1.z*b1.z + b1.w*b1.w;
    s1 = warp_sum(s1);
    s2 = warp_sum(s2);

    float m1 = fmaxf(sqrtf(s1), 1e-12f);
    float m2 = fmaxf(sqrtf(s2), 1e-12f);
    float r1 = 1.0f / m1;
    float r2 = 1.0f / m2;

    float an[8] = { a0.x*r1, a0.y*r1, a0.z*r1, a0.w*r1,
                    a1.x*r1, a1.y*r1, a1.z*r1, a1.w*r1 };
    float bn[8] = { b0.x*r2, b0.y*r2, b0.z*r2, b0.w*r2,
                    b1.x*r2, b1.y*r2, b1.z*r2, b1.w*r2 };

    // quantize 16*an -> 8 e4m3 bytes, coalesced 8B store
    uint16_t q[4];
    #pragma unroll
    for (int k = 0; k < 4; ++k)
        q[k] = f2e4m3x2(QSCALE * an[2*k], QSCALE * an[2*k+1]);
    *(uint2*)(g_z1f8 + (size_t)gw * DIMS + lane * 8) = *(uint2*)q;

    float dp = 0.f;
    #pragma unroll
    for (int k = 0; k < 8; ++k) {
        float d = an[k] - bn[k];
        dp += d * d;
    }
    dp = warp_sum(dp);

    if (lane == 0) {
        g_sq[gw] = s1 * (r1 * r1);
        g_spos[gw] = logf(__expf(-0.5f * dp) + EPS_F) + 1.0f;
    }
}

// ---------------------------------------------------------------------------
// pair kernel: e4m3 mma.sync Gram + exp + reduce (R3-validated structure:
// 2D grid, 2-stage double buffer, 2 syncs per chunk) + fused last-CTA
// finalize. grid = (64, 64), 256 threads = 8 warps (2x4), warp 64x32.
// ---------------------------------------------------------------------------
__global__ void __launch_bounds__(256, 2) pair_kernel(float* __restrict__ out) {
    int ti = blockIdx.y;
    int tj = blockIdx.x;
    if (tj < ti) return;   // uniform per-CTA

    __shared__ __align__(16) uint8_t As[2][BM * BK];
    __shared__ __align__(16) uint8_t Bs[2][BM * BK];
    __shared__ float s_sq[256];
    __shared__ float red[8];
    __shared__ int s_last;

    int tid = threadIdx.x;
    int lane = tid & 31;
    int wid = tid >> 5;
    int wm = wid >> 2;   // 0..1 -> m offset wm*64
    int wn = wid & 3;    // 0..3 -> n offset wn*32

    const uint8_t* gA = g_z1f8 + (size_t)ti * BM * DIMS;
    const uint8_t* gB = g_z1f8 + (size_t)tj * BM * DIMS;

    // stage sq values for the epilogue
    if (tid < 128) s_sq[tid] = g_sq[ti * BM + tid];
    else           s_sq[tid] = g_sq[tj * BM + (tid - 128)];

    float acc[4][4][4];
    #pragma unroll
    for (int mt = 0; mt < 4; ++mt)
        #pragma unroll
        for (int nt = 0; nt < 4; ++nt)
            #pragma unroll
            for (int r = 0; r < 4; ++r)
                acc[mt][nt][r] = 0.f;

    auto issue = [&](int buf, int kt) {
        // A: 128 rows x 64B = 512 x 16B; A+B = 1024 ops / 256 thr = 4 each
        #pragma unroll
        for (int v = 0; v < 4; ++v) {
            int id   = tid + (v << 8);      // 0..1023
            int m    = id >> 9;             // 0 = A, 1 = B
            int r    = (id >> 2) & 127;
            int atom = id & 3;
            int off  = swz(r, atom);
            unsigned dst = (unsigned)__cvta_generic_to_shared(
                (m ? &Bs[buf][off] : &As[buf][off]));
            const uint8_t* src =
                (m ? gB : gA) + r * DIMS + kt * BK + (atom << 4);
            asm volatile("cp.async.cg.shared.global [%0], [%1], 16;\n"
                         :: "r"(dst), "l"(src));
        }
        asm volatile("cp.async.commit_group;\n");
    };

    issue(0, 0);

    int sel = lane >> 3;   // ldmatrix quadrant
    int l7  = lane & 7;

    for (int kt = 0; kt < NCHUNK; ++kt) {
        int buf = kt & 1;
        if (kt < NCHUNK - 1) {
            issue(buf ^ 1, kt + 1);
            asm volatile("cp.async.wait_group 1;\n");
        } else {
            asm volatile("cp.async.wait_group 0;\n");
        }
        __syncthreads();

        // kk in fp8 elements: {0, 32}; 16B atom = 16 elems
        #pragma unroll
        for (int kk = 0; kk < BK; kk += 32) {
            unsigned af[4][4];
            unsigned bf_[4][2];

            // A fragments: m16 x k32 bytes = 16x16 b16-equiv -> ldmatrix x4
            #pragma unroll
            for (int mt = 0; mt < 4; ++mt) {
                int row  = wm * 64 + mt * 16 + ((sel & 1) << 3) + l7;
                int atom = (kk >> 4) + (sel >> 1);
                unsigned ad = (unsigned)__cvta_generic_to_shared(
                    &As[buf][swz(row, atom)]);
                asm volatile(
                    "ldmatrix.sync.aligned.m8n8.x4.shared.b16 "
                    "{%0,%1,%2,%3}, [%4];\n"
                    : "=r"(af[mt][0]), "=r"(af[mt][1]),
                      "=r"(af[mt][2]), "=r"(af[mt][3])
                    : "r"(ad));
            }
            // B fragments: one x4 covers two n-8-tiles (k halves in r0/r1)
            #pragma unroll
            for (int np = 0; np < 2; ++np) {
                int row  = wn * 32 + np * 16 + ((sel >> 1) << 3) + l7;
                int atom = (kk >> 4) + (sel & 1);
                unsigned bd = (unsigned)__cvta_generic_to_shared(
                    &Bs[buf][swz(row, atom)]);
                asm volatile(
                    "ldmatrix.sync.aligned.m8n8.x4.shared.b16 "
                    "{%0,%1,%2,%3}, [%4];\n"
                    : "=r"(bf_[2 * np][0]), "=r"(bf_[2 * np][1]),
                      "=r"(bf_[2 * np + 1][0]), "=r"(bf_[2 * np + 1][1])
                    : "r"(bd));
            }

            #pragma unroll
            for (int mt = 0; mt < 4; ++mt)
                #pragma unroll
                for (int nt = 0; nt < 4; ++nt)
                    asm volatile(
                        "mma.sync.aligned.m16n8k32.row.col.f32.e4m3.e4m3.f32 "
                        "{%0,%1,%2,%3}, {%4,%5,%6,%7}, {%8,%9}, {%0,%1,%2,%3};\n"
                        : "+f"(acc[mt][nt][0]), "+f"(acc[mt][nt][1]),
                          "+f"(acc[mt][nt][2]), "+f"(acc[mt][nt][3])
                        : "r"(af[mt][0]), "r"(af[mt][1]),
                          "r"(af[mt][2]), "r"(af[mt][3]),
                          "r"(bf_[nt][0]), "r"(bf_[nt][1]));
        }
        __syncthreads();
    }

    // epilogue: dot = acc/256; d2 = max(sq_i + sq_j - 2*dot, 0); exp; mask
    int grow  = lane >> 2;
    int gcol2 = (lane & 3) << 1;
    float sum = 0.f;
    #pragma unroll
    for (int mt = 0; mt < 4; ++mt) {
        #pragma unroll
        for (int nt = 0; nt < 4; ++nt) {
            #pragma unroll
            for (int r = 0; r < 4; ++r) {
                int li = wm * 64 + mt * 16 + grow + ((r & 2) ? 8 : 0);
                int lj = wn * 32 + nt * 8 + gcol2 + (r & 1);
                float dot = acc[mt][nt][r] * DOT_SCL;
                float d2 = fmaxf(s_sq[li] + s_sq[128 + lj] - 2.0f * dot, 0.0f);
                float e = __expf(-0.5f * d2);
                if (ti * BM + li == tj * BM + lj) e = 0.f;   // diagonal mask
                sum += e;
            }
        }
    }

    // block reduce -> one partial store per CTA (x2 weight off-diagonal)
    sum = warp_sum(sum);
    if (lane == 0) red[wid] = sum;
    __syncthreads();

    int slot = ti * NT - (ti * (ti - 1)) / 2 + (tj - ti);

    if (tid == 0) {
        float s = 0.f;
        #pragma unroll
        for (int w = 0; w < 8; ++w) s += red[w];
        double contrib = (double)s;
        if (ti != tj) contrib *= 2.0;
        g_partial[slot] = contrib;
        __threadfence();
        int t = atomicAdd(&g_count, 1);
        s_last = (t == NPAIR - 1);
    }
    __syncthreads();

    // last CTA: fused finalize
    if (s_last) {
        __threadfence();
        if (tid == 0) g_count = 0;   // reset for next graph replay

        double dneg = 0.0;
        for (int i = tid; i < NPAIR; i += 256) dneg += g_partial[i];
        #pragma unroll
        for (int o = 16; o > 0; o >>= 1)
            dneg += __shfl_xor_sync(0xffffffffu, dneg, o);
        __shared__ double dred[8];
        if (lane == 0) dred[wid] = dneg;

        float ps = 0.f;
        for (int i = tid; i < NROWS; i += 256) ps += g_spos[i];
        ps = warp_sum(ps);
        __shared__ float fred[8];
        if (lane == 0) fred[wid] = ps;
        __syncthreads();

        if (tid == 0) {
            double neg = 0.0;
            float pos = 0.f;
            #pragma unroll
            for (int w = 0; w < 8; ++w) { neg += dred[w]; pos += fred[w]; }
            double n = (double)NROWS;
            double mean_star = neg / (n * (n - 1.0)) + 1e-8;
            out[0] = (float)(-((double)pos / n) + 1.5 * mean_star);
        }
    }
}

// ---------------------------------------------------------------------------
extern "C" void kernel_launch(void* const* d_in, const int* in_sizes, int n_in,
                              void* d_out, int out_size) {
    const float* z1 = (const float*)d_in[0];
    const float* z2 = (const float*)d_in[1];
    float* out = (float*)d_out;

    prep_kernel<<<NROWS / 8, 256>>>(z1, z2);
    dim3 grid(NT, NT);
    pair_kernel<<<grid, 256>>>(out);
}